// round 15
// baseline (speedup 1.0000x reference)
#include <cuda_runtime.h>
#include <cstdint>

#define BB 128
#define TT 4096
#define KK 64
#define START 62
#define STOP 63
#define NEGV -10000.0f
#define RING 64

__device__ unsigned char g_bp[(size_t)BB * TT * KK];   // 32 MB

__device__ __forceinline__ float frcp(float x) {
    float r; asm("rcp.approx.f32 %0, %1;" : "=f"(r) : "f"(x)); return r;
}
__device__ __forceinline__ unsigned ld_acq(const unsigned* p) {
    unsigned v;
    asm volatile("ld.acquire.cta.shared.u32 %0, [%1];"
                 : "=r"(v) : "l"(__cvta_generic_to_shared(p)) : "memory");
    return v;
}
__device__ __forceinline__ void st_rel(unsigned* p, unsigned v) {
    asm volatile("st.release.cta.shared.u32 [%0], %1;"
                 :: "l"(__cvta_generic_to_shared(p)), "r"(v) : "memory");
}

__global__ __launch_bounds__(128, 1)
void crf_kernel(const float* __restrict__ feats,
                const int*   __restrict__ tags,
                const float* __restrict__ trans,
                float*       __restrict__ out)
{
    __shared__ __align__(16) float a_buf[2][KK];
    __shared__ __align__(16) float dring[RING][KK];   // dring[t&63] = delta_t
    __shared__ __align__(16) float mring[RING][KK];   // mring[t&63] = M_t
    __shared__ unsigned Vcnt;
    __shared__ unsigned bpcnt[2];
    __shared__ float tStop[KK];
    __shared__ float gred[64];
    __shared__ __align__(16) unsigned char stage[2][64 * KK];   // 2 x 4 KB

    const int b    = blockIdx.x;
    const int tid  = threadIdx.x;
    const int wid  = tid >> 5;       // warp -> SMSP (wid % 4)
    const int lane = tid & 31;
    const float* bf = feats + (size_t)b * TT * KK;
    unsigned char* bpb = g_bp + (size_t)b * TT * KK;
    float logscale = 0.0f;

    if (tid == 0) Vcnt = 0;
    if (tid < 2) bpcnt[tid] = 0;
    if (tid < KK) {
        tStop[tid] = trans[STOP * KK + tid];
        a_buf[0][tid] = (tid == START) ? 1.0f : 0.0f;
        dring[0][tid] = (tid == START) ? 0.0f : NEGV;
    }
    __syncthreads();

    if (wid == 0) {
        // ======== FORWARD: single warp, lane owns states (lane, lane+32) ========
        const int j0 = lane, j1 = lane + 32;
        float E0[64], E1[64];
#pragma unroll
        for (int i = 0; i < 64; i++) E0[i] = __expf(trans[j0 * KK + i]);
#pragma unroll
        for (int i = 0; i < 64; i++) E1[i] = __expf(trans[j1 * KK + i]);

        float fa0 = bf[0 * KK + j0], fb0 = bf[0 * KK + j1];
        float fa1 = bf[1 * KK + j0], fb1 = bf[1 * KK + j1];
        float fa2 = bf[2 * KK + j0], fb2 = bf[2 * KK + j1];
        float fa3 = bf[3 * KK + j0], fb3 = bf[3 * KK + j1];
        float ea0 = __expf(fa0), eb0 = __expf(fb0);
        float ea1 = __expf(fa1), eb1 = __expf(fb1);

        int p = 0;
        for (int t = 0; t < TT; t++) {
            float la = 0.f, lb = 0.f;
            if (t + 4 < TT) {
                la = bf[(size_t)(t + 4) * KK + j0];
                lb = bf[(size_t)(t + 4) * KK + j1];
            }

            const float4* av = (const float4*)a_buf[p];
            float c00 = 0.f, c01 = 0.f, c02 = 0.f, c03 = 0.f;
            float c10 = 0.f, c11 = 0.f, c12 = 0.f, c13 = 0.f;
            float a0f = 0.f;
#pragma unroll
            for (int k = 0; k < 16; k++) {
                float4 A = av[k];
                if (k == 0) a0f = A.x;
                c00 = fmaf(E0[4 * k + 0], A.x, c00);
                c01 = fmaf(E0[4 * k + 1], A.y, c01);
                c02 = fmaf(E0[4 * k + 2], A.z, c02);
                c03 = fmaf(E0[4 * k + 3], A.w, c03);
                c10 = fmaf(E1[4 * k + 0], A.x, c10);
                c11 = fmaf(E1[4 * k + 1], A.y, c11);
                c12 = fmaf(E1[4 * k + 2], A.z, c12);
                c13 = fmaf(E1[4 * k + 3], A.w, c13);
            }
            float dot0 = (c00 + c01) + (c02 + c03);
            float dot1 = (c10 + c11) + (c12 + c13);
            float rM = frcp(a0f);

            float lin0 = ea0 * dot0;
            float lin1 = eb0 * dot1;
            if (t == 0) { rM = 1.0f; }
            a_buf[p ^ 1][j0] = lin0 * rM;
            a_buf[p ^ 1][j1] = lin1 * rM;
            __syncwarp();

            if (lane == 0 && t > 0) logscale += __logf(a0f);
            ea0 = ea1; eb0 = eb1;
            ea1 = __expf(fa2); eb1 = __expf(fb2);
            fa0 = fa1; fb0 = fb1; fa1 = fa2; fb1 = fb2;
            fa2 = fa3; fb2 = fb3; fa3 = la;  fb3 = lb;
            p ^= 1;
        }
    } else if (wid == 1) {
        // ======== VITERBI (max only): single warp, lane owns states (lane, lane+32) ========
        const int j0 = lane, j1 = lane + 32;
        float T0[64], T1[64];
#pragma unroll
        for (int i = 0; i < 64; i++) T0[i] = trans[j0 * KK + i];
#pragma unroll
        for (int i = 0; i < 64; i++) T1[i] = trans[j1 * KK + i];

        float fa0 = bf[0 * KK + j0], fb0 = bf[0 * KK + j1];
        float fa1 = bf[1 * KK + j0], fb1 = bf[1 * KK + j1];
        float fa2 = bf[2 * KK + j0], fb2 = bf[2 * KK + j1];
        float fa3 = bf[3 * KK + j0], fb3 = bf[3 * KK + j1];

        for (int t = 0; t < TT; t++) {
            float la = 0.f, lb = 0.f;
            if (t + 4 < TT) {
                la = bf[(size_t)(t + 4) * KK + j0];
                lb = bf[(size_t)(t + 4) * KK + j1];
            }

            // backpressure every 16 steps: ring slot reuse needs BP caught up
            if (t >= RING && (t & 15) == 0) {
                unsigned need = (unsigned)(t - 47);
                for (;;) {
                    unsigned b0 = ld_acq(&bpcnt[0]), b1 = ld_acq(&bpcnt[1]);
                    if (min(b0, b1) >= need) break;
                    __nanosleep(60);
                }
            }

            const float4* dv = (const float4*)dring[t & (RING - 1)];
            float m0, m1, m2, m3, n0, n1, n2, n3;
            {
                float4 D = dv[0];
                m0 = T0[0] + D.x; m1 = T0[1] + D.y; m2 = T0[2] + D.z; m3 = T0[3] + D.w;
                n0 = T1[0] + D.x; n1 = T1[1] + D.y; n2 = T1[2] + D.z; n3 = T1[3] + D.w;
            }
#pragma unroll
            for (int k = 1; k < 16; k++) {
                float4 D = dv[k];
                m0 = fmaxf(m0, T0[4 * k + 0] + D.x);
                m1 = fmaxf(m1, T0[4 * k + 1] + D.y);
                m2 = fmaxf(m2, T0[4 * k + 2] + D.z);
                m3 = fmaxf(m3, T0[4 * k + 3] + D.w);
                n0 = fmaxf(n0, T1[4 * k + 0] + D.x);
                n1 = fmaxf(n1, T1[4 * k + 1] + D.y);
                n2 = fmaxf(n2, T1[4 * k + 2] + D.z);
                n3 = fmaxf(n3, T1[4 * k + 3] + D.w);
            }
            float M0 = fmaxf(fmaxf(m0, m1), fmaxf(m2, m3));
            float M1 = fmaxf(fmaxf(n0, n1), fmaxf(n2, n3));

            int slot = t & (RING - 1), nslot = (t + 1) & (RING - 1);
            mring[slot][j0]  = M0;
            mring[slot][j1]  = M1;
            dring[nslot][j0] = M0 + fa0;
            dring[nslot][j1] = M1 + fb0;
            __syncwarp();
            if (lane == 0 && (t & 15) == 15) st_rel(&Vcnt, (unsigned)(t + 1));

            fa0 = fa1; fb0 = fb1; fa1 = fa2; fb1 = fb2;
            fa2 = fa3; fb2 = fb3; fa3 = la;  fb3 = lb;
        }
    } else {
        // ======== BP warps 2,3: async argmax, 1 state per lane ========
        const int j = (wid - 2) * 32 + lane;   // 0..63
        float T[64];
#pragma unroll
        for (int i = 0; i < 64; i++) T[i] = trans[j * KK + i];

        for (int c = 0; c < TT / 16; c++) {
            unsigned need = (unsigned)(c * 16 + 16);
            while (ld_acq(&Vcnt) < need) { __nanosleep(60); }

            for (int tt = 0; tt < 16; tt++) {
                int tau = c * 16 + tt;
                int slot = tau & (RING - 1);
                const float4* dv = (const float4*)dring[slot];
                float M = mring[slot][j];

                unsigned lo0 = 0, lo1 = 0, lo2 = 0, lo3 = 0;
#pragma unroll
                for (int k = 0; k < 8; k++) {
                    float4 D = dv[k];
                    lo0 |= (T[4 * k + 0] + D.x == M) ? (1u << (4 * k + 0)) : 0u;
                    lo1 |= (T[4 * k + 1] + D.y == M) ? (1u << (4 * k + 1)) : 0u;
                    lo2 |= (T[4 * k + 2] + D.z == M) ? (1u << (4 * k + 2)) : 0u;
                    lo3 |= (T[4 * k + 3] + D.w == M) ? (1u << (4 * k + 3)) : 0u;
                }
                unsigned hi0 = 0, hi1 = 0, hi2 = 0, hi3 = 0;
#pragma unroll
                for (int k = 8; k < 16; k++) {
                    float4 D = dv[k];
                    hi0 |= (T[4 * k + 0] + D.x == M) ? (1u << (4 * k - 32)) : 0u;
                    hi1 |= (T[4 * k + 1] + D.y == M) ? (1u << (4 * k - 31)) : 0u;
                    hi2 |= (T[4 * k + 2] + D.z == M) ? (1u << (4 * k - 30)) : 0u;
                    hi3 |= (T[4 * k + 3] + D.w == M) ? (1u << (4 * k - 29)) : 0u;
                }
                unsigned lo = (lo0 | lo1) | (lo2 | lo3);
                unsigned hi = (hi0 | hi1) | (hi2 | hi3);
                int cand = lo ? (__ffs(lo) - 1) : (32 + __ffs(hi) - 1);
                bpb[(size_t)tau * KK + j] = (unsigned char)cand;
            }
            __syncwarp();
            if (lane == 0) st_rel(&bpcnt[wid - 2], (unsigned)(c * 16 + 16));
        }
    }

    __syncthreads();   // final: a_buf[0] = a_TT, dring[0] = delta_TT (4096 % 64 == 0)

    if (tid < 64) {
        // ---- gold score + nll (warps 0-1) ----
        const int* btags = tags + (size_t)b * TT;
        float g = 0.0f;
        for (int t = tid; t < TT; t += 64) {
            int tag  = btags[t];
            int prev = t ? btags[t - 1] : START;
            g += trans[tag * KK + prev] + bf[(size_t)t * KK + tag];
        }
        gred[tid] = g;
        asm volatile("bar.sync 4, 64;" ::: "memory");
        if (tid == 0) {
            float gold = 0.0f;
            for (int i = 0; i < 64; i++) gold += gred[i];
            gold += tStop[btags[TT - 1]];
            float s = 0.0f;
            for (int i = 0; i < KK; i++) s += a_buf[0][i] * __expf(tStop[i]);
            out[b] = (logscale + __logf(s)) - gold;
        }
    } else {
        // ---- viterbi terminal + backtrack (warps 2-3) ----
        int cur = 0;
        float* po = out + 2 * BB + (size_t)b * TT;
        if (tid == 64) {
            float best = -3.0e38f; int bl2 = 0;
            for (int i = 0; i < KK; i++) {
                float v = dring[0][i] + tStop[i];
                if (v > best) { best = v; bl2 = i; }
            }
            out[BB + b] = best;
            cur = bl2;
            po[TT - 1] = (float)cur;
        }
        {
            const uint4* src = (const uint4*)(bpb + (size_t)63 * 64 * KK);
            uint4* dst = (uint4*)stage[1];
            for (int i = tid - 64; i < 256; i += 64) dst[i] = src[i];
        }
        asm volatile("bar.sync 3, 64;" ::: "memory");
        for (int c = 63; c >= 0; c--) {
            if (tid != 64 && c > 0) {
                const uint4* src = (const uint4*)(bpb + (size_t)(c - 1) * 64 * KK);
                uint4* dst = (uint4*)stage[(c - 1) & 1];
                for (int i = tid - 65; i < 256; i += 63) dst[i] = src[i];
            }
            if (tid == 64) {
                const unsigned char* st = stage[c & 1];
                int tlo = (c == 0) ? 1 : 0;
#pragma unroll 4
                for (int tt = 63; tt >= tlo; tt--) {
                    cur = st[tt * KK + cur];
                    int gt = c * 64 + tt;
                    po[gt - 1] = (float)cur;
                }
            }
            asm volatile("bar.sync 3, 64;" ::: "memory");
        }
    }
}

extern "C" void kernel_launch(void* const* d_in, const int* in_sizes, int n_in,
                              void* d_out, int out_size)
{
    const float* feats = (const float*)d_in[0];
    const int*   tags  = (const int*)d_in[1];
    const float* trans = (const float*)d_in[2];
    float* out = (float*)d_out;
    crf_kernel<<<BB, 128>>>(feats, tags, trans, out);
}